// round 5
// baseline (speedup 1.0000x reference)
#include <cuda_runtime.h>

#define NMAX 50000
#define EMAX 800000

// ---------------- scratch (device globals; no allocation allowed) ----------
__device__ __align__(16) float g_nbr [NMAX*128];
__device__ __align__(16) float g_h   [NMAX*128];
__device__ __align__(16) float g_z1  [NMAX*64];
__device__ __align__(16) float g_as1 [NMAX*8];
__device__ __align__(16) float g_ad1 [NMAX*8];
__device__ __align__(16) float g_m1  [NMAX*8];
__device__ __align__(16) float g_den1[NMAX*8];
__device__ __align__(16) float g_num1[NMAX*64];
__device__ __align__(16) float g_h2  [NMAX*64];
__device__ __align__(16) float g_z2  [NMAX*64];
__device__ __align__(16) float g_as2 [NMAX];
__device__ __align__(16) float g_ad2 [NMAX];
__device__ __align__(16) float g_m2  [NMAX];
__device__ __align__(16) float g_den2[NMAX];
__device__ __align__(16) float g_num2[NMAX*64];
__device__ double g_acc;

// ---------------- helpers ---------------------------------------------------
__device__ __forceinline__ float lrelu(float x){ return x > 0.f ? x : 0.2f*x; }
__device__ __forceinline__ float elu_f(float x){ return x > 0.f ? x : expm1f(x); }

__device__ __forceinline__ void atomicMaxF(float* a, float v){
    if (v >= 0.f) atomicMax((int*)a, __float_as_int(v));
    else          atomicMin((unsigned int*)a, __float_as_uint(v));
}

// sm_90+ vector reduction: 4x fewer atomic ops than scalar atomicAdd
__device__ __forceinline__ void red4(float* p, float4 v){
    asm volatile("red.global.add.v4.f32 [%0], {%1,%2,%3,%4};"
                 :: "l"(p), "f"(v.x), "f"(v.y), "f"(v.z), "f"(v.w) : "memory");
}

// ---------------- kernels ---------------------------------------------------

// zero final accumulator
__global__ void k_init(){ g_acc = 0.0; }

// GraphConv neighbor scatter: warp per edge, lane = float4 chunk (32*4=128)
__global__ void k_scatter(const float* __restrict__ x, const int* __restrict__ src,
                          const int* __restrict__ dst, int E){
    int t = blockIdx.x*blockDim.x + threadIdx.x;
    int w = t >> 5, lane = t & 31;
    if (w >= E) return;
    int s = src[w], d = dst[w];
    float4 v = *(const float4*)(x + (size_t)s*128 + lane*4);
    red4(g_nbr + (size_t)d*128 + lane*4, v);
}

// C[M,Nout] = A[M,K] * B[Nout,K]^T   (optionally accumulate into C)
// 64x64 tile, BK=16, 256 threads, 4x4 register micro-tile
__global__ void k_sgemm(const float* __restrict__ A, const float* __restrict__ B,
                        float* __restrict__ C, int M, int Nout, int K, int accum){
    __shared__ float As[16][64];
    __shared__ float Bs[16][64];
    int tid = threadIdx.x;
    int tx = tid & 15, ty = tid >> 4;
    int bm = blockIdx.x*64, bn = blockIdx.y*64;
    int lr = tid >> 2;          // 0..63
    int lc = (tid & 3) * 4;     // 0,4,8,12
    float acc[4][4] = {};
    for (int k0 = 0; k0 < K; k0 += 16){
        int ar = bm + lr;
        float4 av = make_float4(0.f,0.f,0.f,0.f);
        if (ar < M) av = *(const float4*)(A + (size_t)ar*K + k0 + lc);
        As[lc+0][lr]=av.x; As[lc+1][lr]=av.y; As[lc+2][lr]=av.z; As[lc+3][lr]=av.w;
        int brr = bn + lr;  // Nout is a multiple of 64 -> always valid
        float4 bv = *(const float4*)(B + (size_t)brr*K + k0 + lc);
        Bs[lc+0][lr]=bv.x; Bs[lc+1][lr]=bv.y; Bs[lc+2][lr]=bv.z; Bs[lc+3][lr]=bv.w;
        __syncthreads();
        #pragma unroll
        for (int k = 0; k < 16; k++){
            float4 a = *(const float4*)&As[k][ty*4];
            float4 b = *(const float4*)&Bs[k][tx*4];
            acc[0][0] += a.x*b.x; acc[0][1] += a.x*b.y; acc[0][2] += a.x*b.z; acc[0][3] += a.x*b.w;
            acc[1][0] += a.y*b.x; acc[1][1] += a.y*b.y; acc[1][2] += a.y*b.z; acc[1][3] += a.y*b.w;
            acc[2][0] += a.z*b.x; acc[2][1] += a.z*b.y; acc[2][2] += a.z*b.z; acc[2][3] += a.z*b.w;
            acc[3][0] += a.w*b.x; acc[3][1] += a.w*b.y; acc[3][2] += a.w*b.z; acc[3][3] += a.w*b.w;
        }
        __syncthreads();
    }
    #pragma unroll
    for (int i = 0; i < 4; i++){
        int m = bm + ty*4 + i;
        if (m < M){
            float4* cp = (float4*)(C + (size_t)m*Nout + bn + tx*4);
            float4 v = make_float4(acc[i][0], acc[i][1], acc[i][2], acc[i][3]);
            if (accum){ float4 o = *cp; v.x+=o.x; v.y+=o.y; v.z+=o.z; v.w+=o.w; }
            *cp = v;
        }
    }
}

// h = elu(h + b_rel), elementwise over N*128, bias period 128 (32 float4)
__global__ void k_bias_elu(float* __restrict__ h, const float* __restrict__ b, int total4){
    int i = blockIdx.x*blockDim.x + threadIdx.x;
    if (i >= total4) return;
    float4 v = ((float4*)h)[i];
    float4 bb = ((const float4*)b)[i & 31];
    v.x = elu_f(v.x + bb.x); v.y = elu_f(v.y + bb.y);
    v.z = elu_f(v.z + bb.z); v.w = elu_f(v.w + bb.w);
    ((float4*)h)[i] = v;
}

// GAT1 node pass: alpha_src/alpha_dst per head; m init = self-loop logit
__global__ void k_alpha1(const float* __restrict__ a_src, const float* __restrict__ a_dst, int n){
    __shared__ float sa[64], sd[64];
    int tid = threadIdx.x;
    if (tid < 64){ sa[tid] = a_src[tid]; sd[tid] = a_dst[tid]; }
    __syncthreads();
    int i = blockIdx.x*blockDim.x + tid;
    if (i >= n) return;
    const float* z = g_z1 + (size_t)i*64;
    float zr[64];
    #pragma unroll
    for (int q = 0; q < 16; q++){
        float4 v = ((const float4*)z)[q];
        zr[q*4+0]=v.x; zr[q*4+1]=v.y; zr[q*4+2]=v.z; zr[q*4+3]=v.w;
    }
    #pragma unroll
    for (int h = 0; h < 8; h++){
        float s = 0.f, d = 0.f;
        #pragma unroll
        for (int c = 0; c < 8; c++){
            float zv = zr[h*8+c];
            s += zv * sa[h*8+c];
            d += zv * sd[h*8+c];
        }
        g_as1[(size_t)i*8+h] = s;
        g_ad1[(size_t)i*8+h] = d;
        g_m1 [(size_t)i*8+h] = lrelu(s + d);
    }
}

// GAT1 edge max: one thread per edge, 8 heads
__global__ void k_max1(const int* __restrict__ src, const int* __restrict__ dst, int E){
    int e = blockIdx.x*blockDim.x + threadIdx.x;
    if (e >= E) return;
    int s = src[e], d = dst[e];
    float4 a0 = *(const float4*)(g_as1 + (size_t)s*8);
    float4 a1 = *(const float4*)(g_as1 + (size_t)s*8 + 4);
    float4 d0 = *(const float4*)(g_ad1 + (size_t)d*8);
    float4 d1 = *(const float4*)(g_ad1 + (size_t)d*8 + 4);
    float* m = g_m1 + (size_t)d*8;
    atomicMaxF(m+0, lrelu(a0.x+d0.x)); atomicMaxF(m+1, lrelu(a0.y+d0.y));
    atomicMaxF(m+2, lrelu(a0.z+d0.z)); atomicMaxF(m+3, lrelu(a0.w+d0.w));
    atomicMaxF(m+4, lrelu(a1.x+d1.x)); atomicMaxF(m+5, lrelu(a1.y+d1.y));
    atomicMaxF(m+6, lrelu(a1.z+d1.z)); atomicMaxF(m+7, lrelu(a1.w+d1.w));
}

// GAT1 edge accumulate: 16 lanes per edge; lane sub handles float4 chunk sub
// (head = sub/2); even lanes also add the head's denominator.
__global__ void k_acc1(const int* __restrict__ src, const int* __restrict__ dst, int E){
    int t = blockIdx.x*blockDim.x + threadIdx.x;
    int sub = t & 15, e = t >> 4;
    if (e >= E) return;
    int s = src[e], d = dst[e];
    int head = sub >> 1;
    float asv = g_as1[(size_t)s*8+head];
    float adv = g_ad1[(size_t)d*8+head];
    float mm  = g_m1 [(size_t)d*8+head];
    float ex  = __expf(lrelu(asv + adv) - mm);
    if (!(sub & 1)) atomicAdd(&g_den1[(size_t)d*8+head], ex);
    float4 z = *(const float4*)(g_z1 + (size_t)s*64 + sub*4);
    z.x*=ex; z.y*=ex; z.z*=ex; z.w*=ex;
    red4(g_num1 + (size_t)d*64 + sub*4, z);
}

// GAT1 finalize: add self-loop term, divide, +bias, elu -> h2
__global__ void k_final1(const float* __restrict__ b1, int n){
    int t = blockIdx.x*blockDim.x + threadIdx.x;
    int c = t & 15, i = t >> 4;
    if (i >= n) return;
    int head = c >> 1;
    float asv = g_as1[(size_t)i*8+head];
    float adv = g_ad1[(size_t)i*8+head];
    float mm  = g_m1 [(size_t)i*8+head];
    float den = g_den1[(size_t)i*8+head];
    float exs = __expf(lrelu(asv + adv) - mm);
    float inv = 1.f / (den + exs + 1e-16f);
    float4 z  = *(const float4*)(g_z1  + (size_t)i*64 + c*4);
    float4 nu = *(const float4*)(g_num1 + (size_t)i*64 + c*4);
    float4 bb = ((const float4*)b1)[c];
    float4 o;
    o.x = elu_f((nu.x + exs*z.x)*inv + bb.x);
    o.y = elu_f((nu.y + exs*z.y)*inv + bb.y);
    o.z = elu_f((nu.z + exs*z.z)*inv + bb.z);
    o.w = elu_f((nu.w + exs*z.w)*inv + bb.w);
    *(float4*)(g_h2 + (size_t)i*64 + c*4) = o;
}

// GAT2 node pass (1 head, 64-dim attention vectors)
__global__ void k_alpha2(const float* __restrict__ a_src, const float* __restrict__ a_dst, int n){
    __shared__ float sa[64], sd[64];
    int tid = threadIdx.x;
    if (tid < 64){ sa[tid] = a_src[tid]; sd[tid] = a_dst[tid]; }
    __syncthreads();
    int i = blockIdx.x*blockDim.x + tid;
    if (i >= n) return;
    const float* z = g_z2 + (size_t)i*64;
    float s = 0.f, d = 0.f;
    #pragma unroll
    for (int q = 0; q < 16; q++){
        float4 v = ((const float4*)z)[q];
        s += v.x*sa[q*4+0] + v.y*sa[q*4+1] + v.z*sa[q*4+2] + v.w*sa[q*4+3];
        d += v.x*sd[q*4+0] + v.y*sd[q*4+1] + v.z*sd[q*4+2] + v.w*sd[q*4+3];
    }
    g_as2[i] = s; g_ad2[i] = d; g_m2[i] = lrelu(s + d);
}

__global__ void k_max2(const int* __restrict__ src, const int* __restrict__ dst, int E){
    int e = blockIdx.x*blockDim.x + threadIdx.x;
    if (e >= E) return;
    int s = src[e], d = dst[e];
    atomicMaxF(&g_m2[d], lrelu(g_as2[s] + g_ad2[d]));
}

__global__ void k_acc2(const int* __restrict__ src, const int* __restrict__ dst, int E){
    int t = blockIdx.x*blockDim.x + threadIdx.x;
    int sub = t & 15, e = t >> 4;
    if (e >= E) return;
    int s = src[e], d = dst[e];
    float ex = __expf(lrelu(g_as2[s] + g_ad2[d]) - g_m2[d]);
    if (sub == 0) atomicAdd(&g_den2[d], ex);
    float4 z = *(const float4*)(g_z2 + (size_t)s*64 + sub*4);
    z.x*=ex; z.y*=ex; z.z*=ex; z.w*=ex;
    red4(g_num2 + (size_t)d*64 + sub*4, z);
}

// GAT2 finalize fused with global-mean + regression dot; block-reduced into fp64
__global__ void k_final2(const float* __restrict__ b2, const float* __restrict__ Wr, int n){
    int t = blockIdx.x*blockDim.x + threadIdx.x;
    int c = t & 15, i = t >> 4;
    float part = 0.f;
    if (i < n){
        float exs = __expf(lrelu(g_as2[i] + g_ad2[i]) - g_m2[i]);
        float inv = 1.f / (g_den2[i] + exs + 1e-16f);
        float4 z  = *(const float4*)(g_z2  + (size_t)i*64 + c*4);
        float4 nu = *(const float4*)(g_num2 + (size_t)i*64 + c*4);
        float4 bb = ((const float4*)b2)[c];
        float4 w  = ((const float4*)Wr)[c];
        float vx = (nu.x + exs*z.x)*inv + bb.x;
        float vy = (nu.y + exs*z.y)*inv + bb.y;
        float vz = (nu.z + exs*z.z)*inv + bb.z;
        float vw = (nu.w + exs*z.w)*inv + bb.w;
        part = vx*w.x + vy*w.y + vz*w.z + vw*w.w;
    }
    #pragma unroll
    for (int o = 16; o > 0; o >>= 1) part += __shfl_down_sync(0xffffffffu, part, o);
    __shared__ float ws[8];
    int lane = threadIdx.x & 31, warp = threadIdx.x >> 5;
    if (lane == 0) ws[warp] = part;
    __syncthreads();
    if (threadIdx.x < 8){
        float v = ws[threadIdx.x];
        v += __shfl_down_sync(0xffu, v, 4);
        v += __shfl_down_sync(0xffu, v, 2);
        v += __shfl_down_sync(0xffu, v, 1);
        if (threadIdx.x == 0) atomicAdd(&g_acc, (double)v);
    }
}

__global__ void k_out(const float* __restrict__ br, float* __restrict__ out, int n){
    out[0] = (float)(g_acc / (double)n) + br[0];
}

// ---------------- launch ----------------------------------------------------
extern "C" void kernel_launch(void* const* d_in, const int* in_sizes, int n_in,
                              void* d_out, int out_size){
    const float* x      = (const float*)d_in[0];
    const int*   ei     = (const int*)d_in[1];   // int32: JAX x64 disabled
    const float* W_rel  = (const float*)d_in[2];
    const float* b_rel  = (const float*)d_in[3];
    const float* W_root = (const float*)d_in[4];
    const float* W1     = (const float*)d_in[5];
    const float* a1_src = (const float*)d_in[6];
    const float* a1_dst = (const float*)d_in[7];
    const float* b1     = (const float*)d_in[8];
    const float* W2     = (const float*)d_in[9];
    const float* a2_src = (const float*)d_in[10];
    const float* a2_dst = (const float*)d_in[11];
    const float* b2     = (const float*)d_in[12];
    const float* Wr     = (const float*)d_in[13];
    const float* br     = (const float*)d_in[14];
    float* out = (float*)d_out;

    int n = in_sizes[0] / 128;
    int E = in_sizes[1] / 2;
    const int* src = ei;
    const int* dst = ei + E;

    void *p_nbr, *p_h, *p_z1, *p_den1, *p_num1, *p_h2, *p_z2, *p_den2, *p_num2;
    cudaGetSymbolAddress(&p_nbr,  g_nbr);
    cudaGetSymbolAddress(&p_h,    g_h);
    cudaGetSymbolAddress(&p_z1,   g_z1);
    cudaGetSymbolAddress(&p_den1, g_den1);
    cudaGetSymbolAddress(&p_num1, g_num1);
    cudaGetSymbolAddress(&p_h2,   g_h2);
    cudaGetSymbolAddress(&p_z2,   g_z2);
    cudaGetSymbolAddress(&p_den2, g_den2);
    cudaGetSymbolAddress(&p_num2, g_num2);

    const int T = 256;
    cudaMemsetAsync(p_nbr,  0, (size_t)n*128*sizeof(float));
    cudaMemsetAsync(p_den1, 0, (size_t)n*8*sizeof(float));
    cudaMemsetAsync(p_num1, 0, (size_t)n*64*sizeof(float));
    cudaMemsetAsync(p_den2, 0, (size_t)n*sizeof(float));
    cudaMemsetAsync(p_num2, 0, (size_t)n*64*sizeof(float));

    k_init<<<1, 1>>>();
    k_scatter<<<((size_t)E*32 + T - 1)/T, T>>>(x, src, dst, E);

    // GraphConv: h = x@W_root^T ; h += nbr@W_rel^T ; h = elu(h + b_rel)
    dim3 gc_grid((n + 63)/64, 2);
    k_sgemm<<<gc_grid, T>>>(x, W_root, (float*)p_h, n, 128, 128, 0);
    k_sgemm<<<gc_grid, T>>>((const float*)p_nbr, W_rel, (float*)p_h, n, 128, 128, 1);
    k_bias_elu<<<((size_t)n*32 + T - 1)/T, T>>>((float*)p_h, b_rel, n*32);

    // GAT1
    dim3 g1_grid((n + 63)/64, 1);
    k_sgemm<<<g1_grid, T>>>((const float*)p_h, W1, (float*)p_z1, n, 64, 128, 0);
    k_alpha1<<<(n + T - 1)/T, T>>>(a1_src, a1_dst, n);
    k_max1<<<(E + T - 1)/T, T>>>(src, dst, E);
    k_acc1<<<((size_t)E*16 + T - 1)/T, T>>>(src, dst, E);
    k_final1<<<((size_t)n*16 + T - 1)/T, T>>>(b1, n);

    // GAT2
    k_sgemm<<<g1_grid, T>>>((const float*)p_h2, W2, (float*)p_z2, n, 64, 64, 0);
    k_alpha2<<<(n + T - 1)/T, T>>>(a2_src, a2_dst, n);
    k_max2<<<(E + T - 1)/T, T>>>(src, dst, E);
    k_acc2<<<((size_t)E*16 + T - 1)/T, T>>>(src, dst, E);
    k_final2<<<((size_t)n*16 + T - 1)/T, T>>>(b2, Wr, n);

    k_out<<<1, 1>>>(br, out, n);
}

// round 8
// speedup vs baseline: 1.2237x; 1.2237x over previous
#include <cuda_runtime.h>

#define NMAX 50000
#define EMAX 800000

// ---------------- scratch (device globals; no allocation allowed) ----------
__device__ __align__(16) float g_nbr [NMAX*128];
__device__ __align__(16) float g_h   [NMAX*128];
__device__ __align__(16) float g_z1  [NMAX*64];
__device__ __align__(16) float g_as1 [NMAX*8];
__device__ __align__(16) float g_ad1 [NMAX*8];
__device__ __align__(16) float g_den1[NMAX*8];
__device__ __align__(16) float g_num1[NMAX*64];
__device__ __align__(16) float g_h2  [NMAX*64];
__device__ __align__(16) float g_z2  [NMAX*64];
__device__ __align__(16) float g_as2 [NMAX];
__device__ __align__(16) float g_ad2 [NMAX];
__device__ __align__(16) float g_den2[NMAX];
__device__ __align__(16) float g_num2[NMAX*64];
__device__ double g_acc;

// ---------------- helpers ---------------------------------------------------
__device__ __forceinline__ float lrelu(float x){ return x > 0.f ? x : 0.2f*x; }
__device__ __forceinline__ float elu_f(float x){ return x > 0.f ? x : expm1f(x); }

// sm_90+ vector reduction: 4x fewer atomic ops than scalar atomicAdd
__device__ __forceinline__ void red4(float* p, float4 v){
    asm volatile("red.global.add.v4.f32 [%0], {%1,%2,%3,%4};"
                 :: "l"(p), "f"(v.x), "f"(v.y), "f"(v.z), "f"(v.w) : "memory");
}

// ---------------- kernels ---------------------------------------------------

__global__ void k_init(){ g_acc = 0.0; }

// GraphConv neighbor scatter: warp per edge, lane = float4 chunk (32*4=128)
__global__ void k_scatter(const float* __restrict__ x, const int* __restrict__ src,
                          const int* __restrict__ dst, int E){
    int t = blockIdx.x*blockDim.x + threadIdx.x;
    int w = t >> 5, lane = t & 31;
    if (w >= E) return;
    int s = src[w], d = dst[w];
    float4 v = *(const float4*)(x + (size_t)s*128 + lane*4);
    red4(g_nbr + (size_t)d*128 + lane*4, v);
}

// C[M,Nout] = A0[M,K]*B0^T (+ A1[M,K]*B1^T if dual)   [+bias, elu if mode==1]
// 128x64 block tile, BK=16, 256 threads, 8x4 register micro-tile.
// B matrices are [Nout,K] row-major (dot along K).
__global__ void k_gemm(const float* __restrict__ A0, const float* __restrict__ B0,
                       const float* __restrict__ A1, const float* __restrict__ B1,
                       float* __restrict__ C, const float* __restrict__ bias,
                       int M, int Nout, int K, int dual, int mode){
    __shared__ float As[16][132];
    __shared__ float Bs[16][68];
    int tid = threadIdx.x;
    int tx = tid & 15;          // 0..15 -> 4 cols each (64 cols)
    int ty = tid >> 4;          // 0..15 -> 8 rows each (128 rows)
    int bm = blockIdx.x*128, bn = blockIdx.y*64;
    int lr = tid >> 2;          // 0..63
    int lc = (tid & 3) * 4;     // 0,4,8,12
    float acc[8][4] = {};

    for (int p = 0; p <= dual; p++){
        const float* A = p ? A1 : A0;
        const float* B = p ? B1 : B0;
        for (int k0 = 0; k0 < K; k0 += 16){
            // load A tile 128x16 (2 float4 per thread), transpose into As
            #pragma unroll
            for (int i = 0; i < 2; i++){
                int row = lr + 64*i;
                int ar = bm + row;
                float4 av = make_float4(0.f,0.f,0.f,0.f);
                if (ar < M) av = *(const float4*)(A + (size_t)ar*K + k0 + lc);
                As[lc+0][row]=av.x; As[lc+1][row]=av.y;
                As[lc+2][row]=av.z; As[lc+3][row]=av.w;
            }
            // load B tile 64x16 (1 float4 per thread), transpose into Bs
            {
                int brr = bn + lr;   // Nout multiple of 64 -> in range
                float4 bv = *(const float4*)(B + (size_t)brr*K + k0 + lc);
                Bs[lc+0][lr]=bv.x; Bs[lc+1][lr]=bv.y;
                Bs[lc+2][lr]=bv.z; Bs[lc+3][lr]=bv.w;
            }
            __syncthreads();
            #pragma unroll
            for (int k = 0; k < 16; k++){
                float4 a0 = *(const float4*)&As[k][ty*8];
                float4 a1 = *(const float4*)&As[k][ty*8+4];
                float4 b  = *(const float4*)&Bs[k][tx*4];
                float ar[8] = {a0.x,a0.y,a0.z,a0.w,a1.x,a1.y,a1.z,a1.w};
                float br[4] = {b.x,b.y,b.z,b.w};
                #pragma unroll
                for (int i = 0; i < 8; i++)
                    #pragma unroll
                    for (int j = 0; j < 4; j++)
                        acc[i][j] += ar[i]*br[j];
            }
            __syncthreads();
        }
    }
    float4 bb = make_float4(0.f,0.f,0.f,0.f);
    if (mode == 1) bb = *(const float4*)(bias + bn + tx*4);
    #pragma unroll
    for (int i = 0; i < 8; i++){
        int m = bm + ty*8 + i;
        if (m < M){
            float4 v = make_float4(acc[i][0], acc[i][1], acc[i][2], acc[i][3]);
            if (mode == 1){
                v.x = elu_f(v.x + bb.x); v.y = elu_f(v.y + bb.y);
                v.z = elu_f(v.z + bb.z); v.w = elu_f(v.w + bb.w);
            }
            *(float4*)(C + (size_t)m*Nout + bn + tx*4) = v;
        }
    }
}

// GAT1 node pass: alpha_src/alpha_dst per head
__global__ void k_alpha1(const float* __restrict__ a_src, const float* __restrict__ a_dst, int n){
    __shared__ float sa[64], sd[64];
    int tid = threadIdx.x;
    if (tid < 64){ sa[tid] = a_src[tid]; sd[tid] = a_dst[tid]; }
    __syncthreads();
    int i = blockIdx.x*blockDim.x + tid;
    if (i >= n) return;
    const float* z = g_z1 + (size_t)i*64;
    float zr[64];
    #pragma unroll
    for (int q = 0; q < 16; q++){
        float4 v = ((const float4*)z)[q];
        zr[q*4+0]=v.x; zr[q*4+1]=v.y; zr[q*4+2]=v.z; zr[q*4+3]=v.w;
    }
    #pragma unroll
    for (int h = 0; h < 8; h++){
        float s = 0.f, d = 0.f;
        #pragma unroll
        for (int c = 0; c < 8; c++){
            float zv = zr[h*8+c];
            s += zv * sa[h*8+c];
            d += zv * sd[h*8+c];
        }
        g_as1[(size_t)i*8+h] = s;
        g_ad1[(size_t)i*8+h] = d;
    }
}

// GAT1 edge accumulate (no max shift; logits are O(1) so exp is safe):
// 16 lanes per edge; lane sub handles float4 chunk sub (head = sub/2);
// even lanes also add the head's denominator.
__global__ void k_acc1(const int* __restrict__ src, const int* __restrict__ dst, int E){
    int t = blockIdx.x*blockDim.x + threadIdx.x;
    int sub = t & 15, e = t >> 4;
    if (e >= E) return;
    int s = src[e], d = dst[e];
    int head = sub >> 1;
    float asv = g_as1[(size_t)s*8+head];
    float adv = g_ad1[(size_t)d*8+head];
    float ex  = __expf(lrelu(asv + adv));
    if (!(sub & 1)) atomicAdd(&g_den1[(size_t)d*8+head], ex);
    float4 z = *(const float4*)(g_z1 + (size_t)s*64 + sub*4);
    z.x*=ex; z.y*=ex; z.z*=ex; z.w*=ex;
    red4(g_num1 + (size_t)d*64 + sub*4, z);
}

// GAT1 finalize: add self-loop term, divide, +bias, elu -> h2
__global__ void k_final1(const float* __restrict__ b1, int n){
    int t = blockIdx.x*blockDim.x + threadIdx.x;
    int c = t & 15, i = t >> 4;
    if (i >= n) return;
    int head = c >> 1;
    float asv = g_as1[(size_t)i*8+head];
    float adv = g_ad1[(size_t)i*8+head];
    float den = g_den1[(size_t)i*8+head];
    float exs = __expf(lrelu(asv + adv));
    float inv = 1.f / (den + exs + 1e-16f);
    float4 z  = *(const float4*)(g_z1  + (size_t)i*64 + c*4);
    float4 nu = *(const float4*)(g_num1 + (size_t)i*64 + c*4);
    float4 bb = ((const float4*)b1)[c];
    float4 o;
    o.x = elu_f((nu.x + exs*z.x)*inv + bb.x);
    o.y = elu_f((nu.y + exs*z.y)*inv + bb.y);
    o.z = elu_f((nu.z + exs*z.z)*inv + bb.z);
    o.w = elu_f((nu.w + exs*z.w)*inv + bb.w);
    *(float4*)(g_h2 + (size_t)i*64 + c*4) = o;
}

// GAT2 node pass (1 head, 64-dim attention vectors)
__global__ void k_alpha2(const float* __restrict__ a_src, const float* __restrict__ a_dst, int n){
    __shared__ float sa[64], sd[64];
    int tid = threadIdx.x;
    if (tid < 64){ sa[tid] = a_src[tid]; sd[tid] = a_dst[tid]; }
    __syncthreads();
    int i = blockIdx.x*blockDim.x + tid;
    if (i >= n) return;
    const float* z = g_z2 + (size_t)i*64;
    float s = 0.f, d = 0.f;
    #pragma unroll
    for (int q = 0; q < 16; q++){
        float4 v = ((const float4*)z)[q];
        s += v.x*sa[q*4+0] + v.y*sa[q*4+1] + v.z*sa[q*4+2] + v.w*sa[q*4+3];
        d += v.x*sd[q*4+0] + v.y*sd[q*4+1] + v.z*sd[q*4+2] + v.w*sd[q*4+3];
    }
    g_as2[i] = s; g_ad2[i] = d;
}

__global__ void k_acc2(const int* __restrict__ src, const int* __restrict__ dst, int E){
    int t = blockIdx.x*blockDim.x + threadIdx.x;
    int sub = t & 15, e = t >> 4;
    if (e >= E) return;
    int s = src[e], d = dst[e];
    float ex = __expf(lrelu(g_as2[s] + g_ad2[d]));
    if (sub == 0) atomicAdd(&g_den2[d], ex);
    float4 z = *(const float4*)(g_z2 + (size_t)s*64 + sub*4);
    z.x*=ex; z.y*=ex; z.z*=ex; z.w*=ex;
    red4(g_num2 + (size_t)d*64 + sub*4, z);
}

// GAT2 finalize fused with global-mean + regression dot; block-reduced into fp64
__global__ void k_final2(const float* __restrict__ b2, const float* __restrict__ Wr, int n){
    int t = blockIdx.x*blockDim.x + threadIdx.x;
    int c = t & 15, i = t >> 4;
    float part = 0.f;
    if (i < n){
        float exs = __expf(lrelu(g_as2[i] + g_ad2[i]));
        float inv = 1.f / (g_den2[i] + exs + 1e-16f);
        float4 z  = *(const float4*)(g_z2  + (size_t)i*64 + c*4);
        float4 nu = *(const float4*)(g_num2 + (size_t)i*64 + c*4);
        float4 bb = ((const float4*)b2)[c];
        float4 w  = ((const float4*)Wr)[c];
        float vx = (nu.x + exs*z.x)*inv + bb.x;
        float vy = (nu.y + exs*z.y)*inv + bb.y;
        float vz = (nu.z + exs*z.z)*inv + bb.z;
        float vw = (nu.w + exs*z.w)*inv + bb.w;
        part = vx*w.x + vy*w.y + vz*w.z + vw*w.w;
    }
    #pragma unroll
    for (int o = 16; o > 0; o >>= 1) part += __shfl_down_sync(0xffffffffu, part, o);
    __shared__ float ws[8];
    int lane = threadIdx.x & 31, warp = threadIdx.x >> 5;
    if (lane == 0) ws[warp] = part;
    __syncthreads();
    if (threadIdx.x < 8){
        float v = ws[threadIdx.x];
        v += __shfl_down_sync(0xffu, v, 4);
        v += __shfl_down_sync(0xffu, v, 2);
        v += __shfl_down_sync(0xffu, v, 1);
        if (threadIdx.x == 0) atomicAdd(&g_acc, (double)v);
    }
}

__global__ void k_out(const float* __restrict__ br, float* __restrict__ out, int n){
    out[0] = (float)(g_acc / (double)n) + br[0];
}

// ---------------- launch ----------------------------------------------------
extern "C" void kernel_launch(void* const* d_in, const int* in_sizes, int n_in,
                              void* d_out, int out_size){
    const float* x      = (const float*)d_in[0];
    const int*   ei     = (const int*)d_in[1];   // int32: JAX x64 disabled
    const float* W_rel  = (const float*)d_in[2];
    const float* b_rel  = (const float*)d_in[3];
    const float* W_root = (const float*)d_in[4];
    const float* W1     = (const float*)d_in[5];
    const float* a1_src = (const float*)d_in[6];
    const float* a1_dst = (const float*)d_in[7];
    const float* b1     = (const float*)d_in[8];
    const float* W2     = (const float*)d_in[9];
    const float* a2_src = (const float*)d_in[10];
    const float* a2_dst = (const float*)d_in[11];
    const float* b2     = (const float*)d_in[12];
    const float* Wr     = (const float*)d_in[13];
    const float* br     = (const float*)d_in[14];
    float* out = (float*)d_out;

    int n = in_sizes[0] / 128;
    int E = in_sizes[1] / 2;
    const int* src = ei;
    const int* dst = ei + E;

    void *p_nbr, *p_h, *p_z1, *p_den1, *p_num1, *p_h2, *p_z2, *p_den2, *p_num2;
    cudaGetSymbolAddress(&p_nbr,  g_nbr);
    cudaGetSymbolAddress(&p_h,    g_h);
    cudaGetSymbolAddress(&p_z1,   g_z1);
    cudaGetSymbolAddress(&p_den1, g_den1);
    cudaGetSymbolAddress(&p_num1, g_num1);
    cudaGetSymbolAddress(&p_h2,   g_h2);
    cudaGetSymbolAddress(&p_z2,   g_z2);
    cudaGetSymbolAddress(&p_den2, g_den2);
    cudaGetSymbolAddress(&p_num2, g_num2);

    const int T = 256;
    cudaMemsetAsync(p_nbr,  0, (size_t)n*128*sizeof(float));
    cudaMemsetAsync(p_den1, 0, (size_t)n*8*sizeof(float));
    cudaMemsetAsync(p_num1, 0, (size_t)n*64*sizeof(float));
    cudaMemsetAsync(p_den2, 0, (size_t)n*sizeof(float));
    cudaMemsetAsync(p_num2, 0, (size_t)n*64*sizeof(float));

    k_init<<<1, 1>>>();
    k_scatter<<<((size_t)E*32 + T - 1)/T, T>>>(x, src, dst, E);

    // GraphConv fused: h = elu(x@W_root^T + nbr@W_rel^T + b_rel)
    dim3 gc_grid((n + 127)/128, 2);
    k_gemm<<<gc_grid, T>>>(x, W_root, (const float*)p_nbr, W_rel,
                           (float*)p_h, b_rel, n, 128, 128, 1, 1);

    // GAT1: z1 = h@W1^T
    dim3 g1_grid((n + 127)/128, 1);
    k_gemm<<<g1_grid, T>>>((const float*)p_h, W1, nullptr, nullptr,
                           (float*)p_z1, nullptr, n, 64, 128, 0, 0);
    k_alpha1<<<(n + T - 1)/T, T>>>(a1_src, a1_dst, n);
    k_acc1<<<((size_t)E*16 + T - 1)/T, T>>>(src, dst, E);
    k_final1<<<((size_t)n*16 + T - 1)/T, T>>>(b1, n);

    // GAT2: z2 = h2@W2^T
    k_gemm<<<g1_grid, T>>>((const float*)p_h2, W2, nullptr, nullptr,
                           (float*)p_z2, nullptr, n, 64, 64, 0, 0);
    k_alpha2<<<(n + T - 1)/T, T>>>(a2_src, a2_dst, n);
    k_acc2<<<((size_t)E*16 + T - 1)/T, T>>>(src, dst, E);
    k_final2<<<((size_t)n*16 + T - 1)/T, T>>>(b2, Wr, n);

    k_out<<<1, 1>>>(br, out, n);
}

// round 13
// speedup vs baseline: 1.3642x; 1.1148x over previous
#include <cuda_runtime.h>

#define NMAX 50000
#define EMAX 800000

// ---------------- scratch (device globals; no allocation allowed) ----------
__device__ __align__(16) float g_nbr [NMAX*128];
__device__ __align__(16) float g_h   [NMAX*128];
__device__ __align__(16) float g_z1  [NMAX*64];
__device__ __align__(16) float g_as1 [NMAX*8];
__device__ __align__(16) float g_ad1 [NMAX*8];
__device__ __align__(16) float g_h2  [NMAX*64];
__device__ __align__(16) float g_z2  [NMAX*64];
__device__ __align__(16) float g_as2 [NMAX];
__device__ __align__(16) float g_ad2 [NMAX];
__device__ __align__(16) float g_part[NMAX];
__device__ int g_deg[NMAX];
__device__ int g_off[NMAX];
__device__ int g_cur[NMAX];
__device__ int g_adj[EMAX];

// ---------------- helpers ---------------------------------------------------
__device__ __forceinline__ float lrelu(float x){ return x > 0.f ? x : 0.2f*x; }
__device__ __forceinline__ float elu_f(float x){ return x > 0.f ? x : expm1f(x); }

// ---------------- CSR build -------------------------------------------------
__global__ void k_deg(const int* __restrict__ dst, int E){
    int e = blockIdx.x*blockDim.x + threadIdx.x;
    if (e < E) atomicAdd(&g_deg[dst[e]], 1);
}

// single-block exclusive scan over n degrees -> g_off, g_cur
__global__ void k_scan(int n){
    __shared__ int wsum[32];
    __shared__ int carry;
    int tid = threadIdx.x;
    if (tid == 0) carry = 0;
    __syncthreads();
    for (int base = 0; base < n; base += 1024){
        int i = base + tid;
        int v = (i < n) ? g_deg[i] : 0;
        int x = v;
        #pragma unroll
        for (int o = 1; o < 32; o <<= 1){
            int y = __shfl_up_sync(0xffffffffu, x, o);
            if ((tid & 31) >= o) x += y;
        }
        if ((tid & 31) == 31) wsum[tid >> 5] = x;
        __syncthreads();
        if (tid < 32){
            int w = wsum[tid];
            #pragma unroll
            for (int o = 1; o < 32; o <<= 1){
                int y = __shfl_up_sync(0xffffffffu, w, o);
                if (tid >= o) w += y;
            }
            wsum[tid] = w;
        }
        __syncthreads();
        int incl = x + ((tid >= 32) ? wsum[(tid >> 5) - 1] : 0) + carry;
        if (i < n){ g_off[i] = incl - v; g_cur[i] = incl - v; }
        __syncthreads();
        if (tid == 1023) carry = incl;
        __syncthreads();
    }
}

__global__ void k_fill(const int* __restrict__ src, const int* __restrict__ dst, int E){
    int e = blockIdx.x*blockDim.x + threadIdx.x;
    if (e >= E) return;
    int pos = atomicAdd(&g_cur[dst[e]], 1);
    g_adj[pos] = src[e];
}

// ---------------- GraphConv neighbor gather (warp per node) -----------------
__global__ void k_nbr(const float* __restrict__ x, int n){
    int node = blockIdx.x*8 + (threadIdx.x >> 5);
    int lane = threadIdx.x & 31;
    if (node >= n) return;
    int off = g_off[node], deg = g_deg[node];
    float4 a0 = make_float4(0.f,0.f,0.f,0.f);
    float4 a1 = make_float4(0.f,0.f,0.f,0.f);
    int j = 0;
    for (; j + 1 < deg; j += 2){
        int s0 = g_adj[off+j], s1 = g_adj[off+j+1];
        float4 v0 = *(const float4*)(x + (size_t)s0*128 + lane*4);
        float4 v1 = *(const float4*)(x + (size_t)s1*128 + lane*4);
        a0.x+=v0.x; a0.y+=v0.y; a0.z+=v0.z; a0.w+=v0.w;
        a1.x+=v1.x; a1.y+=v1.y; a1.z+=v1.z; a1.w+=v1.w;
    }
    if (j < deg){
        int s0 = g_adj[off+j];
        float4 v0 = *(const float4*)(x + (size_t)s0*128 + lane*4);
        a0.x+=v0.x; a0.y+=v0.y; a0.z+=v0.z; a0.w+=v0.w;
    }
    a0.x+=a1.x; a0.y+=a1.y; a0.z+=a1.z; a0.w+=a1.w;
    *(float4*)(g_nbr + (size_t)node*128 + lane*4) = a0;
}

// ---------------- GEMM (unchanged from R8) ----------------------------------
__global__ void k_gemm(const float* __restrict__ A0, const float* __restrict__ B0,
                       const float* __restrict__ A1, const float* __restrict__ B1,
                       float* __restrict__ C, const float* __restrict__ bias,
                       int M, int Nout, int K, int dual, int mode){
    __shared__ float As[16][132];
    __shared__ float Bs[16][68];
    int tid = threadIdx.x;
    int tx = tid & 15;
    int ty = tid >> 4;
    int bm = blockIdx.x*128, bn = blockIdx.y*64;
    int lr = tid >> 2;
    int lc = (tid & 3) * 4;
    float acc[8][4] = {};

    for (int p = 0; p <= dual; p++){
        const float* A = p ? A1 : A0;
        const float* B = p ? B1 : B0;
        for (int k0 = 0; k0 < K; k0 += 16){
            #pragma unroll
            for (int i = 0; i < 2; i++){
                int row = lr + 64*i;
                int ar = bm + row;
                float4 av = make_float4(0.f,0.f,0.f,0.f);
                if (ar < M) av = *(const float4*)(A + (size_t)ar*K + k0 + lc);
                As[lc+0][row]=av.x; As[lc+1][row]=av.y;
                As[lc+2][row]=av.z; As[lc+3][row]=av.w;
            }
            {
                int brr = bn + lr;
                float4 bv = *(const float4*)(B + (size_t)brr*K + k0 + lc);
                Bs[lc+0][lr]=bv.x; Bs[lc+1][lr]=bv.y;
                Bs[lc+2][lr]=bv.z; Bs[lc+3][lr]=bv.w;
            }
            __syncthreads();
            #pragma unroll
            for (int k = 0; k < 16; k++){
                float4 a0 = *(const float4*)&As[k][ty*8];
                float4 a1 = *(const float4*)&As[k][ty*8+4];
                float4 b  = *(const float4*)&Bs[k][tx*4];
                float ar[8] = {a0.x,a0.y,a0.z,a0.w,a1.x,a1.y,a1.z,a1.w};
                float br[4] = {b.x,b.y,b.z,b.w};
                #pragma unroll
                for (int i = 0; i < 8; i++)
                    #pragma unroll
                    for (int j = 0; j < 4; j++)
                        acc[i][j] += ar[i]*br[j];
            }
            __syncthreads();
        }
    }
    float4 bb = make_float4(0.f,0.f,0.f,0.f);
    if (mode == 1) bb = *(const float4*)(bias + bn + tx*4);
    #pragma unroll
    for (int i = 0; i < 8; i++){
        int m = bm + ty*8 + i;
        if (m < M){
            float4 v = make_float4(acc[i][0], acc[i][1], acc[i][2], acc[i][3]);
            if (mode == 1){
                v.x = elu_f(v.x + bb.x); v.y = elu_f(v.y + bb.y);
                v.z = elu_f(v.z + bb.z); v.w = elu_f(v.w + bb.w);
            }
            *(float4*)(C + (size_t)m*Nout + bn + tx*4) = v;
        }
    }
}

// ---------------- GAT1 ------------------------------------------------------
__global__ void k_alpha1(const float* __restrict__ a_src, const float* __restrict__ a_dst, int n){
    __shared__ float sa[64], sd[64];
    int tid = threadIdx.x;
    if (tid < 64){ sa[tid] = a_src[tid]; sd[tid] = a_dst[tid]; }
    __syncthreads();
    int i = blockIdx.x*blockDim.x + tid;
    if (i >= n) return;
    const float* z = g_z1 + (size_t)i*64;
    float zr[64];
    #pragma unroll
    for (int q = 0; q < 16; q++){
        float4 v = ((const float4*)z)[q];
        zr[q*4+0]=v.x; zr[q*4+1]=v.y; zr[q*4+2]=v.z; zr[q*4+3]=v.w;
    }
    #pragma unroll
    for (int h = 0; h < 8; h++){
        float s = 0.f, d = 0.f;
        #pragma unroll
        for (int c = 0; c < 8; c++){
            float zv = zr[h*8+c];
            s += zv * sa[h*8+c];
            d += zv * sd[h*8+c];
        }
        g_as1[(size_t)i*8+h] = s;
        g_ad1[(size_t)i*8+h] = d;
    }
}

// warp per node: gather+softmax+aggregate+finalize -> h2
// lane owns cols 2l,2l+1 ; head = l>>2 ; den accumulated redundantly per lane
__global__ void k_gat1(const float* __restrict__ b1, int n){
    int node = blockIdx.x*8 + (threadIdx.x >> 5);
    int lane = threadIdx.x & 31;
    if (node >= n) return;
    int off = g_off[node], deg = g_deg[node];
    int head = lane >> 2;
    float adv = g_ad1[(size_t)node*8 + head];
    float2 num = make_float2(0.f, 0.f);
    float den = 0.f;
    for (int j = 0; j <= deg; j++){           // j==deg -> self loop
        int s = (j < deg) ? g_adj[off+j] : node;
        float asv = g_as1[(size_t)s*8 + head];
        float ex  = __expf(lrelu(asv + adv));
        float2 z  = *(const float2*)(g_z1 + (size_t)s*64 + lane*2);
        num.x += ex*z.x; num.y += ex*z.y; den += ex;
    }
    float inv = 1.f / (den + 1e-16f);
    float2 bb = *(const float2*)(b1 + lane*2);
    float2 o;
    o.x = elu_f(num.x*inv + bb.x);
    o.y = elu_f(num.y*inv + bb.y);
    *(float2*)(g_h2 + (size_t)node*64 + lane*2) = o;
}

// ---------------- GAT2 ------------------------------------------------------
__global__ void k_alpha2(const float* __restrict__ a_src, const float* __restrict__ a_dst, int n){
    __shared__ float sa[64], sd[64];
    int tid = threadIdx.x;
    if (tid < 64){ sa[tid] = a_src[tid]; sd[tid] = a_dst[tid]; }
    __syncthreads();
    int i = blockIdx.x*blockDim.x + tid;
    if (i >= n) return;
    const float* z = g_z2 + (size_t)i*64;
    float s = 0.f, d = 0.f;
    #pragma unroll
    for (int q = 0; q < 16; q++){
        float4 v = ((const float4*)z)[q];
        s += v.x*sa[q*4+0] + v.y*sa[q*4+1] + v.z*sa[q*4+2] + v.w*sa[q*4+3];
        d += v.x*sd[q*4+0] + v.y*sd[q*4+1] + v.z*sd[q*4+2] + v.w*sd[q*4+3];
    }
    g_as2[i] = s; g_ad2[i] = d;
}

// warp per node: gather+softmax+aggregate+bias, fused with Wr dot -> g_part
__global__ void k_gat2(const float* __restrict__ b2, const float* __restrict__ Wr, int n){
    int node = blockIdx.x*8 + (threadIdx.x >> 5);
    int lane = threadIdx.x & 31;
    if (node >= n) return;
    int off = g_off[node], deg = g_deg[node];
    float adv = g_ad2[node];
    float2 num = make_float2(0.f, 0.f);
    float den = 0.f;
    for (int j = 0; j <= deg; j++){
        int s = (j < deg) ? g_adj[off+j] : node;
        float ex = __expf(lrelu(g_as2[s] + adv));
        float2 z = *(const float2*)(g_z2 + (size_t)s*64 + lane*2);
        num.x += ex*z.x; num.y += ex*z.y; den += ex;
    }
    float inv = 1.f / (den + 1e-16f);
    float2 bb = *(const float2*)(b2 + lane*2);
    float2 w  = *(const float2*)(Wr + lane*2);
    float part = (num.x*inv + bb.x)*w.x + (num.y*inv + bb.y)*w.y;
    #pragma unroll
    for (int o = 16; o > 0; o >>= 1) part += __shfl_down_sync(0xffffffffu, part, o);
    if (lane == 0) g_part[node] = part;
}

// deterministic single-block fp64 reduce of g_part -> out
__global__ void k_out(const float* __restrict__ br, float* __restrict__ out, int n){
    __shared__ double ws[32];
    int tid = threadIdx.x;
    double s = 0.0;
    for (int i = tid; i < n; i += 1024) s += (double)g_part[i];
    #pragma unroll
    for (int o = 16; o > 0; o >>= 1) s += __shfl_down_sync(0xffffffffu, s, o);
    if ((tid & 31) == 0) ws[tid >> 5] = s;
    __syncthreads();
    if (tid < 32){
        double v = ws[tid];
        #pragma unroll
        for (int o = 16; o > 0; o >>= 1) v += __shfl_down_sync(0xffffffffu, v, o);
        if (tid == 0) out[0] = (float)(v / (double)n) + br[0];
    }
}

// ---------------- launch ----------------------------------------------------
extern "C" void kernel_launch(void* const* d_in, const int* in_sizes, int n_in,
                              void* d_out, int out_size){
    const float* x      = (const float*)d_in[0];
    const int*   ei     = (const int*)d_in[1];
    const float* W_rel  = (const float*)d_in[2];
    const float* b_rel  = (const float*)d_in[3];
    const float* W_root = (const float*)d_in[4];
    const float* W1     = (const float*)d_in[5];
    const float* a1_src = (const float*)d_in[6];
    const float* a1_dst = (const float*)d_in[7];
    const float* b1     = (const float*)d_in[8];
    const float* W2     = (const float*)d_in[9];
    const float* a2_src = (const float*)d_in[10];
    const float* a2_dst = (const float*)d_in[11];
    const float* b2     = (const float*)d_in[12];
    const float* Wr     = (const float*)d_in[13];
    const float* br     = (const float*)d_in[14];
    float* out = (float*)d_out;

    int n = in_sizes[0] / 128;
    int E = in_sizes[1] / 2;
    const int* src = ei;
    const int* dst = ei + E;

    void *p_nbr, *p_h, *p_z1, *p_h2, *p_z2, *p_deg;
    cudaGetSymbolAddress(&p_nbr, g_nbr);
    cudaGetSymbolAddress(&p_h,   g_h);
    cudaGetSymbolAddress(&p_z1,  g_z1);
    cudaGetSymbolAddress(&p_h2,  g_h2);
    cudaGetSymbolAddress(&p_z2,  g_z2);
    cudaGetSymbolAddress(&p_deg, g_deg);

    const int T = 256;
    cudaMemsetAsync(p_deg, 0, (size_t)n*sizeof(int));

    // CSR build
    k_deg <<<(E + T - 1)/T, T>>>(dst, E);
    k_scan<<<1, 1024>>>(n);
    k_fill<<<(E + T - 1)/T, T>>>(src, dst, E);

    // GraphConv: nbr gather then fused dual-GEMM + bias + elu
    k_nbr<<<(n + 7)/8, 256>>>(x, n);
    dim3 gc_grid((n + 127)/128, 2);
    k_gemm<<<gc_grid, T>>>(x, W_root, (const float*)p_nbr, W_rel,
                           (float*)p_h, b_rel, n, 128, 128, 1, 1);

    // GAT1
    dim3 g1_grid((n + 127)/128, 1);
    k_gemm<<<g1_grid, T>>>((const float*)p_h, W1, nullptr, nullptr,
                           (float*)p_z1, nullptr, n, 64, 128, 0, 0);
    k_alpha1<<<(n + T - 1)/T, T>>>(a1_src, a1_dst, n);
    k_gat1<<<(n + 7)/8, 256>>>(b1, n);

    // GAT2
    k_gemm<<<g1_grid, T>>>((const float*)p_h2, W2, nullptr, nullptr,
                           (float*)p_z2, nullptr, n, 64, 64, 0, 0);
    k_alpha2<<<(n + T - 1)/T, T>>>(a2_src, a2_dst, n);
    k_gat2<<<(n + 7)/8, 256>>>(b2, Wr, n);

    k_out<<<1, 1024>>>(br, out, n);
}